// round 7
// baseline (speedup 1.0000x reference)
#include <cuda_runtime.h>
#include <math.h>

#define BB 2
#define SS 2048
#define EE 1024
#define HH 16
#define DD 64
#define MM (BB * SS)   // 4096

// Scratch: exactly 64 MiB of __device__ globals (proven footprint).
// g_O triple-duty: rounded X for QKV proj -> attention output for O proj.
// g_V stored TRANSPOSED per head: [B,H,D,S] so attention V fragments ldmatrix.
__device__ float g_Q[MM * EE];          // [B,H,S,D] tf32-rounded
__device__ float g_K[MM * EE];          // [B,H,S,D] tf32-rounded
__device__ float g_V[MM * EE];          // [B,H,D,S] tf32-rounded (transposed)
__device__ float g_O[MM * EE];          // [M,E] tf32-rounded (X, then attn O)

// ---------------------------------------------------------------------------
// helpers
// ---------------------------------------------------------------------------
__device__ __forceinline__ unsigned f2tf(float f) {
    unsigned u;
    asm("cvt.rna.tf32.f32 %0, %1;" : "=r"(u) : "f"(f));
    return u;
}
__device__ __forceinline__ float ex2f(float x) {
    float y;
    asm("ex2.approx.f32 %0, %1;" : "=f"(y) : "f"(x));
    return y;
}
__device__ __forceinline__ void mma8(float* c, const unsigned* a, unsigned b0, unsigned b1) {
    asm volatile(
        "mma.sync.aligned.m16n8k8.row.col.f32.tf32.tf32.f32 "
        "{%0,%1,%2,%3}, {%4,%5,%6,%7}, {%8,%9}, {%0,%1,%2,%3};"
        : "+f"(c[0]), "+f"(c[1]), "+f"(c[2]), "+f"(c[3])
        : "r"(a[0]), "r"(a[1]), "r"(a[2]), "r"(a[3]), "r"(b0), "r"(b1));
}
__device__ __forceinline__ void cp16(float* smem, const float* gmem) {
    unsigned s = (unsigned)__cvta_generic_to_shared(smem);
    asm volatile("cp.async.cg.shared.global [%0], [%1], 16;" :: "r"(s), "l"(gmem));
}
// ldmatrix x4 on f32 data viewed as b16 pairs: lane l of matrix i receives
// f32 element (row = l/4, col = l%4) -> exactly the tf32 mma fragment layout.
__device__ __forceinline__ void ldsm4(unsigned* r, const float* p) {
    unsigned a = (unsigned)__cvta_generic_to_shared(p);
    asm volatile("ldmatrix.sync.aligned.m8n8.x4.shared.b16 {%0,%1,%2,%3}, [%4];"
                 : "=r"(r[0]), "=r"(r[1]), "=r"(r[2]), "=r"(r[3]) : "r"(a));
}

// ---------------------------------------------------------------------------
// round x -> tf32, written straight into g_O
// ---------------------------------------------------------------------------
__global__ void __launch_bounds__(256) round_x_kernel(const float4* __restrict__ src)
{
    int i = blockIdx.x * 256 + threadIdx.x;
    float4 v = src[i];
    v.x = __uint_as_float(f2tf(v.x));
    v.y = __uint_as_float(f2tf(v.y));
    v.z = __uint_as_float(f2tf(v.z));
    v.w = __uint_as_float(f2tf(v.w));
    ((float4*)g_O)[i] = v;
}

// ---------------------------------------------------------------------------
// Tensor-core NT GEMM: C[M,N] = A[M,K] @ W[N,K]^T + bias
// A from g_O (pre-rounded tf32, raw ldmatrix). W raw fp32, ldmatrix + reg cvt.
// 128x128x32 tiles, 256 threads. 3-stage cp.async ring: one __syncthreads per
// iteration, prefetch issued BEFORE compute -> ~2 iterations of load latency
// hiding. 2 CTAs/SM (110.6KB smem each).
// MODE 0: z selects W/bias; z=0,1 -> Q/K [B,H,S,D]; z=2 -> V transposed [B,H,D,S].
// MODE 1: plain [M,E] fp32 output to Yout.
// ---------------------------------------------------------------------------
#define GLD 36                       // padded smem row stride (floats)
#define GSTAGE (128 * GLD)           // floats per operand per stage
#define NSTAGE 3

template <int MODE>
__global__ void __launch_bounds__(256)
gemm_tc(const float* __restrict__ W0, const float* __restrict__ b0v,
        const float* __restrict__ W1, const float* __restrict__ b1v,
        const float* __restrict__ W2, const float* __restrict__ b2v,
        float* __restrict__ Yout)
{
    extern __shared__ float sh[];

    const float* Ag = g_O;
    const float* W;
    const float* bias;
    int z = 0;
    if (MODE == 0) {
        z    = blockIdx.z;
        W    = (z == 0) ? W0 : (z == 1) ? W1 : W2;
        bias = (z == 0) ? b0v : (z == 1) ? b1v : b2v;
    } else {
        W    = W0;
        bias = b0v;
    }

    const int tid  = threadIdx.x;
    const int warp = tid >> 5;
    const int lane = tid & 31;
    const int g    = lane >> 2;
    const int q    = lane & 3;
    const int m0   = blockIdx.x * 128;
    const int n0   = blockIdx.y * 128;
    const int wm   = (warp >> 1) * 32;   // 4 warp-rows of 32
    const int wn   = (warp & 1) * 64;    // 2 warp-cols of 64

    const int lr = tid >> 1;             // load row 0..127
    const int lc = (tid & 1) * 16;       // load col base 0/16

    // ldmatrix per-lane address components
    const int a_row = (lane & 15);
    const int a_col = (lane & 16) >> 2;
    const int b_row = (lane & 7) + ((lane & 16) >> 1);
    const int b_col = (lane & 8) >> 1;

    float acc[2][8][4];
#pragma unroll
    for (int mt = 0; mt < 2; mt++)
#pragma unroll
        for (int nt = 0; nt < 8; nt++)
#pragma unroll
            for (int t = 0; t < 4; t++) acc[mt][nt][t] = 0.0f;

    // prologue: stages 0,1 into slots 0,1
#pragma unroll
    for (int st = 0; st < 2; st++) {
        float* As = sh + st * 2 * GSTAGE;
        float* Bs = As + GSTAGE;
        int k0 = st * 32;
#pragma unroll
        for (int i = 0; i < 4; i++) {
            int cc = lc + i * 4;
            cp16(As + lr * GLD + cc, Ag + (size_t)(m0 + lr) * EE + k0 + cc);
            cp16(Bs + lr * GLD + cc, W  + (size_t)(n0 + lr) * EE + k0 + cc);
        }
        asm volatile("cp.async.commit_group;");
    }

    const int NITER = EE / 32;
    int slot = 0;                        // it % 3
    int pslot = 2;                       // (it+2) % 3
    for (int it = 0; it < NITER; it++) {
        asm volatile("cp.async.wait_group 1;");
        __syncthreads();                 // all warps done reading slot pslot (iter it-1)

        // prefetch stage it+2 into slot (it+2)%3 BEFORE compute
        if (it + 2 < NITER) {
            float* As2 = sh + pslot * 2 * GSTAGE;
            float* Bs2 = As2 + GSTAGE;
            int k0 = (it + 2) * 32;
#pragma unroll
            for (int i = 0; i < 4; i++) {
                int cc = lc + i * 4;
                cp16(As2 + lr * GLD + cc, Ag + (size_t)(m0 + lr) * EE + k0 + cc);
                cp16(Bs2 + lr * GLD + cc, W  + (size_t)(n0 + lr) * EE + k0 + cc);
            }
        }
        asm volatile("cp.async.commit_group;");

        const float* As = sh + slot * 2 * GSTAGE;
        const float* Bs = As + GSTAGE;

#pragma unroll
        for (int kk = 0; kk < 32; kk += 8) {
            unsigned af[2][4];
            ldsm4(af[0], As + (wm +      a_row) * GLD + kk + a_col);
            ldsm4(af[1], As + (wm + 16 + a_row) * GLD + kk + a_col);
#pragma unroll
            for (int p = 0; p < 4; p++) {
                unsigned bq[4];
                ldsm4(bq, Bs + (wn + p * 16 + b_row) * GLD + kk + b_col);
                unsigned c0 = f2tf(__uint_as_float(bq[0]));
                unsigned c1 = f2tf(__uint_as_float(bq[1]));
                unsigned c2 = f2tf(__uint_as_float(bq[2]));
                unsigned c3 = f2tf(__uint_as_float(bq[3]));
                mma8(acc[0][2 * p],     af[0], c0, c1);
                mma8(acc[1][2 * p],     af[1], c0, c1);
                mma8(acc[0][2 * p + 1], af[0], c2, c3);
                mma8(acc[1][2 * p + 1], af[1], c2, c3);
            }
        }

        slot  = (slot == 2)  ? 0 : slot + 1;
        pslot = (pslot == 2) ? 0 : pslot + 1;
    }

    // epilogue: direct register writes
#pragma unroll
    for (int mt = 0; mt < 2; mt++) {
#pragma unroll
        for (int nt = 0; nt < 8; nt++) {
            int r = m0 + wm + mt * 16 + g;
            int c = n0 + wn + nt * 8 + 2 * q;
            float bx = bias[c], by = bias[c + 1];
            float v0 = acc[mt][nt][0] + bx, v1 = acc[mt][nt][1] + by;
            float v2 = acc[mt][nt][2] + bx, v3 = acc[mt][nt][3] + by;
            if (MODE == 0) {
                int b = r >> 11, s = r & (SS - 1);
                int h = c >> 6, d = c & 63;
                if (z == 2) {
                    // V transposed: [B,H,D,S]
                    float* dst = g_V + (((size_t)(b * HH + h)) * DD + d) * SS + s;
                    dst[0]      = __uint_as_float(f2tf(v0));
                    dst[SS]     = __uint_as_float(f2tf(v1));
                    dst[8]      = __uint_as_float(f2tf(v2));
                    dst[SS + 8] = __uint_as_float(f2tf(v3));
                } else {
                    float* dst = (z == 0) ? g_Q : g_K;
                    dst += (((size_t)(b * HH + h)) * SS + s) * DD + d;
                    float2 u0; u0.x = __uint_as_float(f2tf(v0)); u0.y = __uint_as_float(f2tf(v1));
                    float2 u1; u1.x = __uint_as_float(f2tf(v2)); u1.y = __uint_as_float(f2tf(v3));
                    *(float2*)dst = u0;
                    *(float2*)(dst + 8 * DD) = u1;
                }
            } else {
                float* dst = Yout + (size_t)r * EE + c;
                float2 u0; u0.x = v0; u0.y = v1;
                float2 u1; u1.x = v2; u1.y = v3;
                *(float2*)dst = u0;
                *(float2*)(dst + 8 * EE) = u1;
            }
        }
    }
}

// ---------------------------------------------------------------------------
// Flash attention, register-resident, mma.sync m16n8k8 tf32, ldmatrix
// fragments for K and (transposed) V. Writes tf32-rounded O into g_O.
// (unchanged from R5)
// ---------------------------------------------------------------------------
#define LDS_ 68
#define TILE_F (64 * LDS_)
#define QSTAGE_F (128 * LDS_)

__global__ void __launch_bounds__(256, 1) attn_kernel()
{
    extern __shared__ float sh[];
    float* Qs = sh;
    float* Kbuf0 = sh + QSTAGE_F;
    float* Vbuf0 = Kbuf0 + TILE_F;
    float* Kbuf1 = Vbuf0 + TILE_F;
    float* Vbuf1 = Kbuf1 + TILE_F;

    const int tid  = threadIdx.x;
    const int warp = tid >> 5;
    const int lane = tid & 31;
    const int g    = lane >> 2;
    const int q    = lane & 3;
    const int bh   = blockIdx.y;
    const int q0   = blockIdx.x * 128;

    const float* Qg = g_Q + (size_t)bh * SS * DD;
    const float* Kg = g_K + (size_t)bh * SS * DD;
    const float* Vg = g_V + (size_t)bh * SS * DD;   // transposed [D][S]

    const int b_row = (lane & 7) + ((lane & 16) >> 1);
    const int b_col = (lane & 8) >> 1;

#pragma unroll
    for (int t = 0; t < 2; t++) {
        float* Kd = t ? Kbuf1 : Kbuf0;
        float* Vd = t ? Vbuf1 : Vbuf0;
#pragma unroll
        for (int i = 0; i < 4; i++) {
            int idx = tid + i * 256;
            int r = idx >> 4, c = (idx & 15) * 4;
            cp16(Kd + r * LDS_ + c, Kg + (size_t)(t * 64 + r) * 64 + c);
            cp16(Vd + r * LDS_ + c, Vg + (size_t)r * SS + t * 64 + c);
        }
        asm volatile("cp.async.commit_group;");
    }

#pragma unroll
    for (int i = 0; i < 8; i++) {
        int idx = tid + i * 256;
        int r = idx >> 4, c = (idx & 15) * 4;
        *(float4*)(Qs + r * LDS_ + c) = *(const float4*)(Qg + (size_t)(q0 + r) * 64 + c);
    }
    __syncthreads();

    const float qscale = 0.125f * 1.44269504088896340736f;
    const int rbase = warp * 16;
    unsigned qf[8][4];
#pragma unroll
    for (int ks = 0; ks < 8; ks++) {
        qf[ks][0] = f2tf(Qs[(rbase + g)     * LDS_ + 8 * ks + q]     * qscale);
        qf[ks][1] = f2tf(Qs[(rbase + g + 8) * LDS_ + 8 * ks + q]     * qscale);
        qf[ks][2] = f2tf(Qs[(rbase + g)     * LDS_ + 8 * ks + q + 4] * qscale);
        qf[ks][3] = f2tf(Qs[(rbase + g + 8) * LDS_ + 8 * ks + q + 4] * qscale);
    }

    float o[8][4];
#pragma unroll
    for (int i = 0; i < 8; i++)
#pragma unroll
        for (int k = 0; k < 4; k++) o[i][k] = 0.0f;
    float m0 = -INFINITY, m1 = -INFINITY, l0 = 0.0f, l1 = 0.0f;

    const int src1 = (lane & ~3) | (q >> 1);
    const int src2 = src1 + 2;
    const bool odd = q & 1;

    for (int j = 0; j < SS / 64; j++) {
        asm volatile("cp.async.wait_group 1;");
        __syncthreads();
        const float* K = (j & 1) ? Kbuf1 : Kbuf0;
        const float* V = (j & 1) ? Vbuf1 : Vbuf0;

        float s[8][4];
#pragma unroll
        for (int nt = 0; nt < 8; nt++)
            s[nt][0] = s[nt][1] = s[nt][2] = s[nt][3] = 0.0f;
#pragma unroll
        for (int ks = 0; ks < 8; ks++) {
#pragma unroll
            for (int p = 0; p < 4; p++) {
                unsigned kb[4];
                ldsm4(kb, K + (p * 16 + b_row) * LDS_ + 8 * ks + b_col);
                mma8(s[2 * p],     qf[ks], kb[0], kb[1]);
                mma8(s[2 * p + 1], qf[ks], kb[2], kb[3]);
            }
        }

        float mx0 = -INFINITY, mx1 = -INFINITY;
#pragma unroll
        for (int nt = 0; nt < 8; nt++) {
            mx0 = fmaxf(mx0, fmaxf(s[nt][0], s[nt][1]));
            mx1 = fmaxf(mx1, fmaxf(s[nt][2], s[nt][3]));
        }
        mx0 = fmaxf(mx0, __shfl_xor_sync(0xffffffffu, mx0, 1));
        mx0 = fmaxf(mx0, __shfl_xor_sync(0xffffffffu, mx0, 2));
        mx1 = fmaxf(mx1, __shfl_xor_sync(0xffffffffu, mx1, 1));
        mx1 = fmaxf(mx1, __shfl_xor_sync(0xffffffffu, mx1, 2));
        float mn0 = fmaxf(m0, mx0), mn1 = fmaxf(m1, mx1);
        float cr0 = ex2f(m0 - mn0), cr1 = ex2f(m1 - mn1);
        float rs0 = 0.0f, rs1 = 0.0f;
#pragma unroll
        for (int nt = 0; nt < 8; nt++) {
            s[nt][0] = ex2f(s[nt][0] - mn0);
            s[nt][1] = ex2f(s[nt][1] - mn0);
            s[nt][2] = ex2f(s[nt][2] - mn1);
            s[nt][3] = ex2f(s[nt][3] - mn1);
            rs0 += s[nt][0] + s[nt][1];
            rs1 += s[nt][2] + s[nt][3];
        }
        rs0 += __shfl_xor_sync(0xffffffffu, rs0, 1);
        rs0 += __shfl_xor_sync(0xffffffffu, rs0, 2);
        rs1 += __shfl_xor_sync(0xffffffffu, rs1, 1);
        rs1 += __shfl_xor_sync(0xffffffffu, rs1, 2);
        l0 = l0 * cr0 + rs0;
        l1 = l1 * cr1 + rs1;
#pragma unroll
        for (int nt = 0; nt < 8; nt++) {
            o[nt][0] *= cr0; o[nt][1] *= cr0;
            o[nt][2] *= cr1; o[nt][3] *= cr1;
        }
        m0 = mn0; m1 = mn1;

        unsigned pf[8][4];
#pragma unroll
        for (int nt = 0; nt < 8; nt++) {
            float v00 = __shfl_sync(0xffffffffu, s[nt][0], src1);
            float v01 = __shfl_sync(0xffffffffu, s[nt][1], src1);
            float v10 = __shfl_sync(0xffffffffu, s[nt][2], src1);
            float v11 = __shfl_sync(0xffffffffu, s[nt][3], src1);
            float w00 = __shfl_sync(0xffffffffu, s[nt][0], src2);
            float w01 = __shfl_sync(0xffffffffu, s[nt][1], src2);
            float w10 = __shfl_sync(0xffffffffu, s[nt][2], src2);
            float w11 = __shfl_sync(0xffffffffu, s[nt][3], src2);
            pf[nt][0] = f2tf(odd ? v01 : v00);
            pf[nt][1] = f2tf(odd ? v11 : v10);
            pf[nt][2] = f2tf(odd ? w01 : w00);
            pf[nt][3] = f2tf(odd ? w11 : w10);
        }

#pragma unroll
        for (int t = 0; t < 8; t++) {
#pragma unroll
            for (int p = 0; p < 4; p++) {
                unsigned vb[4];
                ldsm4(vb, V + (p * 16 + b_row) * LDS_ + 8 * t + b_col);
                mma8(o[2 * p],     pf[t], vb[0], vb[1]);
                mma8(o[2 * p + 1], pf[t], vb[2], vb[3]);
            }
        }

        __syncthreads();
        if (j + 2 < SS / 64) {
            float* Kd = (j & 1) ? Kbuf1 : Kbuf0;
            float* Vd = (j & 1) ? Vbuf1 : Vbuf0;
#pragma unroll
            for (int i = 0; i < 4; i++) {
                int idx = tid + i * 256;
                int r = idx >> 4, c = (idx & 15) * 4;
                cp16(Kd + r * LDS_ + c, Kg + (size_t)((j + 2) * 64 + r) * 64 + c);
                cp16(Vd + r * LDS_ + c, Vg + (size_t)r * SS + (j + 2) * 64 + c);
            }
        }
        asm volatile("cp.async.commit_group;");
    }

    float inv0 = 1.0f / l0, inv1 = 1.0f / l1;
    int b = bh / HH, h = bh % HH;
    size_t row0 = (size_t)b * SS + q0 + rbase + g;
    float* d0 = g_O + row0 * EE + h * DD;
    float* d1 = d0 + 8 * EE;
#pragma unroll
    for (int nt2 = 0; nt2 < 8; nt2++) {
        float2 u;
        u.x = __uint_as_float(f2tf(o[nt2][0] * inv0));
        u.y = __uint_as_float(f2tf(o[nt2][1] * inv0));
        *(float2*)(d0 + 8 * nt2 + 2 * q) = u;
        float2 w;
        w.x = __uint_as_float(f2tf(o[nt2][2] * inv1));
        w.y = __uint_as_float(f2tf(o[nt2][3] * inv1));
        *(float2*)(d1 + 8 * nt2 + 2 * q) = w;
    }
}

// ---------------------------------------------------------------------------
extern "C" void kernel_launch(void* const* d_in, const int* in_sizes, int n_in,
                              void* d_out, int out_size)
{
    const float* x  = (const float*)d_in[0];
    const float* Wq = (const float*)d_in[1];
    const float* bq = (const float*)d_in[2];
    const float* Wk = (const float*)d_in[3];
    const float* bk = (const float*)d_in[4];
    const float* Wv = (const float*)d_in[5];
    const float* bv = (const float*)d_in[6];
    const float* Wo = (const float*)d_in[7];
    const float* bo = (const float*)d_in[8];
    float* out = (float*)d_out;

    (void)in_sizes; (void)n_in; (void)out_size;

    const int gemm_smem = NSTAGE * 2 * GSTAGE * sizeof(float);  // 110592
    cudaFuncSetAttribute(gemm_tc<0>, cudaFuncAttributeMaxDynamicSharedMemorySize, gemm_smem);
    cudaFuncSetAttribute(gemm_tc<1>, cudaFuncAttributeMaxDynamicSharedMemorySize, gemm_smem);
    const int attn_smem = (QSTAGE_F + 4 * TILE_F) * sizeof(float);
    cudaFuncSetAttribute(attn_kernel, cudaFuncAttributeMaxDynamicSharedMemorySize, attn_smem);

    // x -> tf32-rounded into g_O (dead until attention writes it)
    round_x_kernel<<<MM * EE / 4 / 256, 256>>>((const float4*)x);

    dim3 gq(MM / 128, EE / 128, 3);
    gemm_tc<0><<<gq, 256, gemm_smem>>>(Wq, bq, Wk, bk, Wv, bv, nullptr);

    attn_kernel<<<dim3(SS / 128, BB * HH), 256, attn_smem>>>();

    dim3 go(MM / 128, EE / 128, 1);
    gemm_tc<1><<<go, 256, gemm_smem>>>(Wo, bo, nullptr, nullptr, nullptr, nullptr, out);
}

// round 9
// speedup vs baseline: 1.1232x; 1.1232x over previous
#include <cuda_runtime.h>
#include <math.h>

#define BB 2
#define SS 2048
#define EE 1024
#define HH 16
#define DD 64
#define MM (BB * SS)   // 4096

__device__ float g_Q[MM * EE];   // [B,H,S,D] tf32-rounded
__device__ float g_K[MM * EE];   // [B,H,S,D] tf32-rounded
__device__ float g_V[MM * EE];   // [B,H,D,S] tf32-rounded (transposed)
__device__ float g_O[MM * EE];   // [M,E] tf32-rounded (X, then attn O)

// ---------------------------------------------------------------------------
// helpers
// ---------------------------------------------------------------------------
__device__ __forceinline__ unsigned f2tf(float f) {
    unsigned u; asm("cvt.rna.tf32.f32 %0, %1;" : "=r"(u) : "f"(f)); return u;
}
__device__ __forceinline__ float ex2f(float x) {
    float y; asm("ex2.approx.f32 %0, %1;" : "=f"(y) : "f"(x)); return y;
}
__device__ __forceinline__ void mma8(float* c, const unsigned* a, unsigned b0, unsigned b1) {
    asm volatile(
        "mma.sync.aligned.m16n8k8.row.col.f32.tf32.tf32.f32 "
        "{%0,%1,%2,%3}, {%4,%5,%6,%7}, {%8,%9}, {%0,%1,%2,%3};"
        : "+f"(c[0]), "+f"(c[1]), "+f"(c[2]), "+f"(c[3])
        : "r"(a[0]), "r"(a[1]), "r"(a[2]), "r"(a[3]), "r"(b0), "r"(b1));
}
__device__ __forceinline__ void cp16(float* smem, const float* gmem) {
    unsigned s = (unsigned)__cvta_generic_to_shared(smem);
    asm volatile("cp.async.cg.shared.global [%0], [%1], 16;" :: "r"(s), "l"(gmem));
}
__device__ __forceinline__ void ldsm4(unsigned* r, const float* p) {
    unsigned a = (unsigned)__cvta_generic_to_shared(p);
    asm volatile("ldmatrix.sync.aligned.m8n8.x4.shared.b16 {%0,%1,%2,%3}, [%4];"
                 : "=r"(r[0]), "=r"(r[1]), "=r"(r[2]), "=r"(r[3]) : "r"(a));
}

// ---------------------------------------------------------------------------
// round x -> tf32, written straight into g_O
// ---------------------------------------------------------------------------
__global__ void __launch_bounds__(256) round_x_kernel(const float4* __restrict__ src)
{
    int i = blockIdx.x * 256 + threadIdx.x;
    float4 v = src[i];
    v.x = __uint_as_float(f2tf(v.x)); v.y = __uint_as_float(f2tf(v.y));
    v.z = __uint_as_float(f2tf(v.z)); v.w = __uint_as_float(f2tf(v.w));
    ((float4*)g_O)[i] = v;
}

// ---------------------------------------------------------------------------
// Tensor-core NT GEMM: C[M,N] = A[M,K] @ W[N,K]^T + bias
// 128x128x32 CTA tile, 512 threads, 32x32 warp tiles (16 warps) -> low regs,
// 2 CTAs/SM = 32 warps/SM for latency hiding. 2-stage cp.async ring.
// A from g_O (pre-rounded tf32, raw bits). W raw fp32, inline cvt.
// MODE 0: z=0,1 -> Q/K [B,H,S,D]; z=2 -> V transposed [B,H,D,S].
// MODE 1: plain [M,E] fp32 to Yout.
// ---------------------------------------------------------------------------
#define GLD 36
#define GSTAGE (128 * GLD)

template <int MODE>
__global__ void __launch_bounds__(512, 2)
gemm_tc(const float* __restrict__ W0, const float* __restrict__ b0v,
        const float* __restrict__ W1, const float* __restrict__ b1v,
        const float* __restrict__ W2, const float* __restrict__ b2v,
        float* __restrict__ Yout)
{
    extern __shared__ float sh[];

    const float* Ag = g_O;
    const float* W; const float* bias; int z = 0;
    if (MODE == 0) {
        z    = blockIdx.z;
        W    = (z == 0) ? W0 : (z == 1) ? W1 : W2;
        bias = (z == 0) ? b0v : (z == 1) ? b1v : b2v;
    } else { W = W0; bias = b0v; }

    const int tid  = threadIdx.x;
    const int warp = tid >> 5;          // 0..15
    const int lane = tid & 31;
    const int g    = lane >> 2;
    const int q    = lane & 3;
    const int m0   = blockIdx.x * 128;
    const int n0   = blockIdx.y * 128;
    const int wm   = (warp >> 2) * 32;  // warp row block (4 rows of warps)
    const int wn   = (warp & 3) * 32;   // warp col block (4 cols of warps)

    // loaders: 512 threads, 128 rows x 32 cols per operand stage
    const int lr = tid >> 2;            // row 0..127
    const int lc = (tid & 3) * 4;       // col 0,4,8,12 (then +16)

    // ldmatrix per-lane address components
    const int a_row = (lane & 15);
    const int a_col = (lane & 16) >> 2;
    const int b_row = (lane & 7) + ((lane & 16) >> 1);
    const int b_col = (lane & 8) >> 1;

    float acc[2][4][4];
#pragma unroll
    for (int mt = 0; mt < 2; mt++)
#pragma unroll
        for (int nt = 0; nt < 4; nt++)
#pragma unroll
            for (int t = 0; t < 4; t++) acc[mt][nt][t] = 0.0f;

    // prologue: stages 0,1
#pragma unroll
    for (int st = 0; st < 2; st++) {
        float* As = sh + st * 2 * GSTAGE;
        float* Bs = As + GSTAGE;
        int k0 = st * 32;
        cp16(As + lr * GLD + lc,      Ag + (size_t)(m0 + lr) * EE + k0 + lc);
        cp16(As + lr * GLD + lc + 16, Ag + (size_t)(m0 + lr) * EE + k0 + lc + 16);
        cp16(Bs + lr * GLD + lc,      W  + (size_t)(n0 + lr) * EE + k0 + lc);
        cp16(Bs + lr * GLD + lc + 16, W  + (size_t)(n0 + lr) * EE + k0 + lc + 16);
        asm volatile("cp.async.commit_group;");
    }

    const int NITER = EE / 32;
    for (int it = 0; it < NITER; it++) {
        asm volatile("cp.async.wait_group 1;");
        __syncthreads();
        const float* As = sh + (it & 1) * 2 * GSTAGE;
        const float* Bs = As + GSTAGE;

#pragma unroll
        for (int kk = 0; kk < 32; kk += 8) {
            unsigned af[2][4];
            ldsm4(af[0], As + (wm +      a_row) * GLD + kk + a_col);
            ldsm4(af[1], As + (wm + 16 + a_row) * GLD + kk + a_col);
#pragma unroll
            for (int p = 0; p < 2; p++) {
                unsigned bq[4];
                ldsm4(bq, Bs + (wn + p * 16 + b_row) * GLD + kk + b_col);
                unsigned c0 = f2tf(__uint_as_float(bq[0]));
                unsigned c1 = f2tf(__uint_as_float(bq[1]));
                unsigned c2 = f2tf(__uint_as_float(bq[2]));
                unsigned c3 = f2tf(__uint_as_float(bq[3]));
                mma8(acc[0][2 * p],     af[0], c0, c1);
                mma8(acc[1][2 * p],     af[1], c0, c1);
                mma8(acc[0][2 * p + 1], af[0], c2, c3);
                mma8(acc[1][2 * p + 1], af[1], c2, c3);
            }
        }

        __syncthreads();
        if (it + 2 < NITER) {
            float* As2 = sh + (it & 1) * 2 * GSTAGE;
            float* Bs2 = As2 + GSTAGE;
            int k0 = (it + 2) * 32;
            cp16(As2 + lr * GLD + lc,      Ag + (size_t)(m0 + lr) * EE + k0 + lc);
            cp16(As2 + lr * GLD + lc + 16, Ag + (size_t)(m0 + lr) * EE + k0 + lc + 16);
            cp16(Bs2 + lr * GLD + lc,      W  + (size_t)(n0 + lr) * EE + k0 + lc);
            cp16(Bs2 + lr * GLD + lc + 16, W  + (size_t)(n0 + lr) * EE + k0 + lc + 16);
        }
        asm volatile("cp.async.commit_group;");
    }

    // epilogue: direct register writes
#pragma unroll
    for (int mt = 0; mt < 2; mt++) {
#pragma unroll
        for (int nt = 0; nt < 4; nt++) {
            int r = m0 + wm + mt * 16 + g;
            int c = n0 + wn + nt * 8 + 2 * q;
            float bx = bias[c], by = bias[c + 1];
            float v0 = acc[mt][nt][0] + bx, v1 = acc[mt][nt][1] + by;
            float v2 = acc[mt][nt][2] + bx, v3 = acc[mt][nt][3] + by;
            if (MODE == 0) {
                int b = r >> 11, s = r & (SS - 1);
                int h = c >> 6, d = c & 63;
                if (z == 2) {
                    float* dst = g_V + (((size_t)(b * HH + h)) * DD + d) * SS + s;
                    dst[0]      = __uint_as_float(f2tf(v0));
                    dst[SS]     = __uint_as_float(f2tf(v1));
                    dst[8]      = __uint_as_float(f2tf(v2));
                    dst[SS + 8] = __uint_as_float(f2tf(v3));
                } else {
                    float* dst = (z == 0) ? g_Q : g_K;
                    dst += (((size_t)(b * HH + h)) * SS + s) * DD + d;
                    float2 u0; u0.x = __uint_as_float(f2tf(v0)); u0.y = __uint_as_float(f2tf(v1));
                    float2 u1; u1.x = __uint_as_float(f2tf(v2)); u1.y = __uint_as_float(f2tf(v3));
                    *(float2*)dst = u0;
                    *(float2*)(dst + 8 * DD) = u1;
                }
            } else {
                float* dst = Yout + (size_t)r * EE + c;
                float2 u0; u0.x = v0; u0.y = v1;
                float2 u1; u1.x = v2; u1.y = v3;
                *(float2*)dst = u0;
                *(float2*)(dst + 8 * EE) = u1;
            }
        }
    }
}

// ---------------------------------------------------------------------------
// Flash attention (unchanged from R5): register-resident mma.sync tf32,
// ldmatrix K / transposed-V fragments. Writes tf32-rounded O into g_O.
// ---------------------------------------------------------------------------
#define LDS_ 68
#define TILE_F (64 * LDS_)
#define QSTAGE_F (128 * LDS_)

__global__ void __launch_bounds__(256, 1) attn_kernel()
{
    extern __shared__ float sh[];
    float* Qs = sh;
    float* Kbuf0 = sh + QSTAGE_F;
    float* Vbuf0 = Kbuf0 + TILE_F;
    float* Kbuf1 = Vbuf0 + TILE_F;
    float* Vbuf1 = Kbuf1 + TILE_F;

    const int tid  = threadIdx.x;
    const int warp = tid >> 5;
    const int lane = tid & 31;
    const int g    = lane >> 2;
    const int q    = lane & 3;
    const int bh   = blockIdx.y;
    const int q0   = blockIdx.x * 128;

    const float* Qg = g_Q + (size_t)bh * SS * DD;
    const float* Kg = g_K + (size_t)bh * SS * DD;
    const float* Vg = g_V + (size_t)bh * SS * DD;   // transposed [D][S]

    const int b_row = (lane & 7) + ((lane & 16) >> 1);
    const int b_col = (lane & 8) >> 1;

#pragma unroll
    for (int t = 0; t < 2; t++) {
        float* Kd = t ? Kbuf1 : Kbuf0;
        float* Vd = t ? Vbuf1 : Vbuf0;
#pragma unroll
        for (int i = 0; i < 4; i++) {
            int idx = tid + i * 256;
            int r = idx >> 4, c = (idx & 15) * 4;
            cp16(Kd + r * LDS_ + c, Kg + (size_t)(t * 64 + r) * 64 + c);
            cp16(Vd + r * LDS_ + c, Vg + (size_t)r * SS + t * 64 + c);
        }
        asm volatile("cp.async.commit_group;");
    }

#pragma unroll
    for (int i = 0; i < 8; i++) {
        int idx = tid + i * 256;
        int r = idx >> 4, c = (idx & 15) * 4;
        *(float4*)(Qs + r * LDS_ + c) = *(const float4*)(Qg + (size_t)(q0 + r) * 64 + c);
    }
    __syncthreads();

    const float qscale = 0.125f * 1.44269504088896340736f;
    const int rbase = warp * 16;
    unsigned qf[8][4];
#pragma unroll
    for (int ks = 0; ks < 8; ks++) {
        qf[ks][0] = f2tf(Qs[(rbase + g)     * LDS_ + 8 * ks + q]     * qscale);
        qf[ks][1] = f2tf(Qs[(rbase + g + 8) * LDS_ + 8 * ks + q]     * qscale);
        qf[ks][2] = f2tf(Qs[(rbase + g)     * LDS_ + 8 * ks + q + 4] * qscale);
        qf[ks][3] = f2tf(Qs[(rbase + g + 8) * LDS_ + 8 * ks + q + 4] * qscale);
    }

    float o[8][4];
#pragma unroll
    for (int i = 0; i < 8; i++)
#pragma unroll
        for (int k = 0; k < 4; k++) o[i][k] = 0.0f;
    float m0 = -INFINITY, m1 = -INFINITY, l0 = 0.0f, l1 = 0.0f;

    const int src1 = (lane & ~3) | (q >> 1);
    const int src2 = src1 + 2;
    const bool odd = q & 1;

    for (int j = 0; j < SS / 64; j++) {
        asm volatile("cp.async.wait_group 1;");
        __syncthreads();
        const float* K = (j & 1) ? Kbuf1 : Kbuf0;
        const float* V = (j & 1) ? Vbuf1 : Vbuf0;

        float s[8][4];
#pragma unroll
        for (int nt = 0; nt < 8; nt++)
            s[nt][0] = s[nt][1] = s[nt][2] = s[nt][3] = 0.0f;
#pragma unroll
        for (int ks = 0; ks < 8; ks++) {
#pragma unroll
            for (int p = 0; p < 4; p++) {
                unsigned kb[4];
                ldsm4(kb, K + (p * 16 + b_row) * LDS_ + 8 * ks + b_col);
                mma8(s[2 * p],     qf[ks], kb[0], kb[1]);
                mma8(s[2 * p + 1], qf[ks], kb[2], kb[3]);
            }
        }

        float mx0 = -INFINITY, mx1 = -INFINITY;
#pragma unroll
        for (int nt = 0; nt < 8; nt++) {
            mx0 = fmaxf(mx0, fmaxf(s[nt][0], s[nt][1]));
            mx1 = fmaxf(mx1, fmaxf(s[nt][2], s[nt][3]));
        }
        mx0 = fmaxf(mx0, __shfl_xor_sync(0xffffffffu, mx0, 1));
        mx0 = fmaxf(mx0, __shfl_xor_sync(0xffffffffu, mx0, 2));
        mx1 = fmaxf(mx1, __shfl_xor_sync(0xffffffffu, mx1, 1));
        mx1 = fmaxf(mx1, __shfl_xor_sync(0xffffffffu, mx1, 2));
        float mn0 = fmaxf(m0, mx0), mn1 = fmaxf(m1, mx1);
        float cr0 = ex2f(m0 - mn0), cr1 = ex2f(m1 - mn1);
        float rs0 = 0.0f, rs1 = 0.0f;
#pragma unroll
        for (int nt = 0; nt < 8; nt++) {
            s[nt][0] = ex2f(s[nt][0] - mn0);
            s[nt][1] = ex2f(s[nt][1] - mn0);
            s[nt][2] = ex2f(s[nt][2] - mn1);
            s[nt][3] = ex2f(s[nt][3] - mn1);
            rs0 += s[nt][0] + s[nt][1];
            rs1 += s[nt][2] + s[nt][3];
        }
        rs0 += __shfl_xor_sync(0xffffffffu, rs0, 1);
        rs0 += __shfl_xor_sync(0xffffffffu, rs0, 2);
        rs1 += __shfl_xor_sync(0xffffffffu, rs1, 1);
        rs1 += __shfl_xor_sync(0xffffffffu, rs1, 2);
        l0 = l0 * cr0 + rs0;
        l1 = l1 * cr1 + rs1;
#pragma unroll
        for (int nt = 0; nt < 8; nt++) {
            o[nt][0] *= cr0; o[nt][1] *= cr0;
            o[nt][2] *= cr1; o[nt][3] *= cr1;
        }
        m0 = mn0; m1 = mn1;

        unsigned pf[8][4];
#pragma unroll
        for (int nt = 0; nt < 8; nt++) {
            float v00 = __shfl_sync(0xffffffffu, s[nt][0], src1);
            float v01 = __shfl_sync(0xffffffffu, s[nt][1], src1);
            float v10 = __shfl_sync(0xffffffffu, s[nt][2], src1);
            float v11 = __shfl_sync(0xffffffffu, s[nt][3], src1);
            float w00 = __shfl_sync(0xffffffffu, s[nt][0], src2);
            float w01 = __shfl_sync(0xffffffffu, s[nt][1], src2);
            float w10 = __shfl_sync(0xffffffffu, s[nt][2], src2);
            float w11 = __shfl_sync(0xffffffffu, s[nt][3], src2);
            pf[nt][0] = f2tf(odd ? v01 : v00);
            pf[nt][1] = f2tf(odd ? v11 : v10);
            pf[nt][2] = f2tf(odd ? w01 : w00);
            pf[nt][3] = f2tf(odd ? w11 : w10);
        }

#pragma unroll
        for (int t = 0; t < 8; t++) {
#pragma unroll
            for (int p = 0; p < 4; p++) {
                unsigned vb[4];
                ldsm4(vb, V + (p * 16 + b_row) * LDS_ + 8 * t + b_col);
                mma8(o[2 * p],     pf[t], vb[0], vb[1]);
                mma8(o[2 * p + 1], pf[t], vb[2], vb[3]);
            }
        }

        __syncthreads();
        if (j + 2 < SS / 64) {
            float* Kd = (j & 1) ? Kbuf1 : Kbuf0;
            float* Vd = (j & 1) ? Vbuf1 : Vbuf0;
#pragma unroll
            for (int i = 0; i < 4; i++) {
                int idx = tid + i * 256;
                int r = idx >> 4, c = (idx & 15) * 4;
                cp16(Kd + r * LDS_ + c, Kg + (size_t)((j + 2) * 64 + r) * 64 + c);
                cp16(Vd + r * LDS_ + c, Vg + (size_t)r * SS + (j + 2) * 64 + c);
            }
        }
        asm volatile("cp.async.commit_group;");
    }

    float inv0 = 1.0f / l0, inv1 = 1.0f / l1;
    int b = bh / HH, h = bh % HH;
    size_t row0 = (size_t)b * SS + q0 + rbase + g;
    float* d0 = g_O + row0 * EE + h * DD;
    float* d1 = d0 + 8 * EE;
#pragma unroll
    for (int nt2 = 0; nt2 < 8; nt2++) {
        float2 u;
        u.x = __uint_as_float(f2tf(o[nt2][0] * inv0));
        u.y = __uint_as_float(f2tf(o[nt2][1] * inv0));
        *(float2*)(d0 + 8 * nt2 + 2 * q) = u;
        float2 w;
        w.x = __uint_as_float(f2tf(o[nt2][2] * inv1));
        w.y = __uint_as_float(f2tf(o[nt2][3] * inv1));
        *(float2*)(d1 + 8 * nt2 + 2 * q) = w;
    }
}

// ---------------------------------------------------------------------------
extern "C" void kernel_launch(void* const* d_in, const int* in_sizes, int n_in,
                              void* d_out, int out_size)
{
    const float* x  = (const float*)d_in[0];
    const float* Wq = (const float*)d_in[1];
    const float* bq = (const float*)d_in[2];
    const float* Wk = (const float*)d_in[3];
    const float* bk = (const float*)d_in[4];
    const float* Wv = (const float*)d_in[5];
    const float* bv = (const float*)d_in[6];
    const float* Wo = (const float*)d_in[7];
    const float* bo = (const float*)d_in[8];
    float* out = (float*)d_out;

    (void)in_sizes; (void)n_in; (void)out_size;

    const int gemm_smem = 2 * 2 * GSTAGE * sizeof(float);   // 73728
    cudaFuncSetAttribute(gemm_tc<0>, cudaFuncAttributeMaxDynamicSharedMemorySize, gemm_smem);
    cudaFuncSetAttribute(gemm_tc<1>, cudaFuncAttributeMaxDynamicSharedMemorySize, gemm_smem);
    const int attn_smem = (QSTAGE_F + 4 * TILE_F) * sizeof(float);
    cudaFuncSetAttribute(attn_kernel, cudaFuncAttributeMaxDynamicSharedMemorySize, attn_smem);

    round_x_kernel<<<MM * EE / 4 / 256, 256>>>((const float4*)x);

    dim3 gq(MM / 128, EE / 128, 3);
    gemm_tc<0><<<gq, 512, gemm_smem>>>(Wq, bq, Wk, bk, Wv, bv, nullptr);

    attn_kernel<<<dim3(SS / 128, BB * HH), 256, attn_smem>>>();

    dim3 go(MM / 128, EE / 128, 1);
    gemm_tc<1><<<go, 512, gemm_smem>>>(Wo, bo, nullptr, nullptr, nullptr, nullptr, out);
}

// round 10
// speedup vs baseline: 1.2470x; 1.1102x over previous
#include <cuda_runtime.h>
#include <math.h>

#define BB 2
#define SS 2048
#define EE 1024
#define HH 16
#define DD 64
#define MM (BB * SS)   // 4096

__device__ float g_Q[MM * EE];   // [B,H,S,D] tf32-rounded
__device__ float g_K[MM * EE];   // [B,H,S,D] tf32-rounded
__device__ float g_V[MM * EE];   // [B,H,D,S] tf32-rounded (transposed)
__device__ float g_O[MM * EE];   // [M,E] tf32-rounded (X, then attn O)

// ---------------------------------------------------------------------------
// helpers
// ---------------------------------------------------------------------------
__device__ __forceinline__ unsigned f2tf(float f) {
    unsigned u; asm("cvt.rna.tf32.f32 %0, %1;" : "=r"(u) : "f"(f)); return u;
}
__device__ __forceinline__ float ex2f(float x) {
    float y; asm("ex2.approx.f32 %0, %1;" : "=f"(y) : "f"(x)); return y;
}
__device__ __forceinline__ void mma8(float* c, const unsigned* a, unsigned b0, unsigned b1) {
    asm volatile(
        "mma.sync.aligned.m16n8k8.row.col.f32.tf32.tf32.f32 "
        "{%0,%1,%2,%3}, {%4,%5,%6,%7}, {%8,%9}, {%0,%1,%2,%3};"
        : "+f"(c[0]), "+f"(c[1]), "+f"(c[2]), "+f"(c[3])
        : "r"(a[0]), "r"(a[1]), "r"(a[2]), "r"(a[3]), "r"(b0), "r"(b1));
}
__device__ __forceinline__ void cp16(float* smem, const float* gmem) {
    unsigned s = (unsigned)__cvta_generic_to_shared(smem);
    asm volatile("cp.async.cg.shared.global [%0], [%1], 16;" :: "r"(s), "l"(gmem));
}
__device__ __forceinline__ void ldsm4(unsigned* r, const float* p) {
    unsigned a = (unsigned)__cvta_generic_to_shared(p);
    asm volatile("ldmatrix.sync.aligned.m8n8.x4.shared.b16 {%0,%1,%2,%3}, [%4];"
                 : "=r"(r[0]), "=r"(r[1]), "=r"(r[2]), "=r"(r[3]) : "r"(a));
}

// ---------------------------------------------------------------------------
// round x -> tf32, written straight into g_O
// ---------------------------------------------------------------------------
__global__ void __launch_bounds__(256) round_x_kernel(const float4* __restrict__ src)
{
    int i = blockIdx.x * 256 + threadIdx.x;
    float4 v = src[i];
    v.x = __uint_as_float(f2tf(v.x)); v.y = __uint_as_float(f2tf(v.y));
    v.z = __uint_as_float(f2tf(v.z)); v.w = __uint_as_float(f2tf(v.w));
    ((float4*)g_O)[i] = v;
}

// ---------------------------------------------------------------------------
// Tensor-core NT GEMM: C[M,N] = A[M,K] @ W[N,K]^T + bias
// 128x128x32 CTA tile, 128 threads = 4 warps of 64x64 -> 2x fewer smem bytes
// per MAC (crossbar was the binding constraint). 3 CTAs/SM (72KB smem each),
// 2-stage cp.async ring. A from g_O (pre-rounded tf32), W raw fp32 inline cvt.
// MODE 0: z=0,1 -> Q/K [B,H,S,D]; z=2 -> V transposed [B,H,D,S].
// MODE 1: plain [M,E] fp32 to Yout.
// ---------------------------------------------------------------------------
#define GLD 36
#define GSTAGE (128 * GLD)

template <int MODE>
__global__ void __launch_bounds__(128, 3)
gemm_tc(const float* __restrict__ W0, const float* __restrict__ b0v,
        const float* __restrict__ W1, const float* __restrict__ b1v,
        const float* __restrict__ W2, const float* __restrict__ b2v,
        float* __restrict__ Yout)
{
    extern __shared__ float sh[];

    const float* Ag = g_O;
    const float* W; const float* bias; int z = 0;
    if (MODE == 0) {
        z    = blockIdx.z;
        W    = (z == 0) ? W0 : (z == 1) ? W1 : W2;
        bias = (z == 0) ? b0v : (z == 1) ? b1v : b2v;
    } else { W = W0; bias = b0v; }

    const int tid  = threadIdx.x;
    const int warp = tid >> 5;          // 0..3
    const int lane = tid & 31;
    const int g    = lane >> 2;
    const int q    = lane & 3;
    const int m0   = blockIdx.x * 128;
    const int n0   = blockIdx.y * 128;
    const int wm   = (warp >> 1) * 64;  // 2x2 warp grid of 64x64 tiles
    const int wn   = (warp & 1) * 64;

    // ldmatrix per-lane address components
    const int a_row = (lane & 15);
    const int a_col = (lane & 16) >> 2;
    const int b_row = (lane & 7) + ((lane & 16) >> 1);
    const int b_col = (lane & 8) >> 1;

    float acc[4][8][4];                 // 128 accumulator regs
#pragma unroll
    for (int mt = 0; mt < 4; mt++)
#pragma unroll
        for (int nt = 0; nt < 8; nt++)
#pragma unroll
            for (int t = 0; t < 4; t++) acc[mt][nt][t] = 0.0f;

    // loaders: 128 threads, 8 float4 per operand per stage
    auto load_stage = [&](int k0, float* As, float* Bs) {
#pragma unroll
        for (int i = 0; i < 8; i++) {
            int idx = tid + i * 128;
            int row = idx >> 3, c4 = (idx & 7) * 4;
            cp16(As + row * GLD + c4, Ag + (size_t)(m0 + row) * EE + k0 + c4);
        }
#pragma unroll
        for (int i = 0; i < 8; i++) {
            int idx = tid + i * 128;
            int row = idx >> 3, c4 = (idx & 7) * 4;
            cp16(Bs + row * GLD + c4, W + (size_t)(n0 + row) * EE + k0 + c4);
        }
    };

    load_stage(0, sh, sh + GSTAGE);
    asm volatile("cp.async.commit_group;");
    load_stage(32, sh + 2 * GSTAGE, sh + 3 * GSTAGE);
    asm volatile("cp.async.commit_group;");

    const int NITER = EE / 32;
    for (int it = 0; it < NITER; it++) {
        asm volatile("cp.async.wait_group 1;");
        __syncthreads();
        const float* As = sh + (it & 1) * 2 * GSTAGE;
        const float* Bs = As + GSTAGE;

#pragma unroll
        for (int kk = 0; kk < 32; kk += 8) {
            unsigned af[4][4];
#pragma unroll
            for (int mt = 0; mt < 4; mt++)
                ldsm4(af[mt], As + (wm + mt * 16 + a_row) * GLD + kk + a_col);
#pragma unroll
            for (int p = 0; p < 4; p++) {
                unsigned bq[4];
                ldsm4(bq, Bs + (wn + p * 16 + b_row) * GLD + kk + b_col);
                unsigned c0 = f2tf(__uint_as_float(bq[0]));
                unsigned c1 = f2tf(__uint_as_float(bq[1]));
                unsigned c2 = f2tf(__uint_as_float(bq[2]));
                unsigned c3 = f2tf(__uint_as_float(bq[3]));
#pragma unroll
                for (int mt = 0; mt < 4; mt++) {
                    mma8(acc[mt][2 * p],     af[mt], c0, c1);
                    mma8(acc[mt][2 * p + 1], af[mt], c2, c3);
                }
            }
        }

        __syncthreads();
        if (it + 2 < NITER) {
            float* As2 = sh + (it & 1) * 2 * GSTAGE;
            load_stage((it + 2) * 32, As2, As2 + GSTAGE);
        }
        asm volatile("cp.async.commit_group;");
    }

    // epilogue: direct register writes
#pragma unroll
    for (int mt = 0; mt < 4; mt++) {
#pragma unroll
        for (int nt = 0; nt < 8; nt++) {
            int r = m0 + wm + mt * 16 + g;
            int c = n0 + wn + nt * 8 + 2 * q;
            float bx = bias[c], by = bias[c + 1];
            float v0 = acc[mt][nt][0] + bx, v1 = acc[mt][nt][1] + by;
            float v2 = acc[mt][nt][2] + bx, v3 = acc[mt][nt][3] + by;
            if (MODE == 0) {
                int b = r >> 11, s = r & (SS - 1);
                int h = c >> 6, d = c & 63;
                if (z == 2) {
                    float* dst = g_V + (((size_t)(b * HH + h)) * DD + d) * SS + s;
                    dst[0]      = __uint_as_float(f2tf(v0));
                    dst[SS]     = __uint_as_float(f2tf(v1));
                    dst[8]      = __uint_as_float(f2tf(v2));
                    dst[SS + 8] = __uint_as_float(f2tf(v3));
                } else {
                    float* dst = (z == 0) ? g_Q : g_K;
                    dst += (((size_t)(b * HH + h)) * SS + s) * DD + d;
                    float2 u0; u0.x = __uint_as_float(f2tf(v0)); u0.y = __uint_as_float(f2tf(v1));
                    float2 u1; u1.x = __uint_as_float(f2tf(v2)); u1.y = __uint_as_float(f2tf(v3));
                    *(float2*)dst = u0;
                    *(float2*)(dst + 8 * DD) = u1;
                }
            } else {
                float* dst = Yout + (size_t)r * EE + c;
                float2 u0; u0.x = v0; u0.y = v1;
                float2 u1; u1.x = v2; u1.y = v3;
                *(float2*)dst = u0;
                *(float2*)(dst + 8 * EE) = u1;
            }
        }
    }
}

// ---------------------------------------------------------------------------
// Flash attention (unchanged from R5): register-resident mma.sync tf32,
// ldmatrix K / transposed-V fragments. Writes tf32-rounded O into g_O.
// ---------------------------------------------------------------------------
#define LDS_ 68
#define TILE_F (64 * LDS_)
#define QSTAGE_F (128 * LDS_)

__global__ void __launch_bounds__(256, 1) attn_kernel()
{
    extern __shared__ float sh[];
    float* Qs = sh;
    float* Kbuf0 = sh + QSTAGE_F;
    float* Vbuf0 = Kbuf0 + TILE_F;
    float* Kbuf1 = Vbuf0 + TILE_F;
    float* Vbuf1 = Kbuf1 + TILE_F;

    const int tid  = threadIdx.x;
    const int warp = tid >> 5;
    const int lane = tid & 31;
    const int g    = lane >> 2;
    const int q    = lane & 3;
    const int bh   = blockIdx.y;
    const int q0   = blockIdx.x * 128;

    const float* Qg = g_Q + (size_t)bh * SS * DD;
    const float* Kg = g_K + (size_t)bh * SS * DD;
    const float* Vg = g_V + (size_t)bh * SS * DD;   // transposed [D][S]

    const int b_row = (lane & 7) + ((lane & 16) >> 1);
    const int b_col = (lane & 8) >> 1;

#pragma unroll
    for (int t = 0; t < 2; t++) {
        float* Kd = t ? Kbuf1 : Kbuf0;
        float* Vd = t ? Vbuf1 : Vbuf0;
#pragma unroll
        for (int i = 0; i < 4; i++) {
            int idx = tid + i * 256;
            int r = idx >> 4, c = (idx & 15) * 4;
            cp16(Kd + r * LDS_ + c, Kg + (size_t)(t * 64 + r) * 64 + c);
            cp16(Vd + r * LDS_ + c, Vg + (size_t)r * SS + t * 64 + c);
        }
        asm volatile("cp.async.commit_group;");
    }

#pragma unroll
    for (int i = 0; i < 8; i++) {
        int idx = tid + i * 256;
        int r = idx >> 4, c = (idx & 15) * 4;
        *(float4*)(Qs + r * LDS_ + c) = *(const float4*)(Qg + (size_t)(q0 + r) * 64 + c);
    }
    __syncthreads();

    const float qscale = 0.125f * 1.44269504088896340736f;
    const int rbase = warp * 16;
    unsigned qf[8][4];
#pragma unroll
    for (int ks = 0; ks < 8; ks++) {
        qf[ks][0] = f2tf(Qs[(rbase + g)     * LDS_ + 8 * ks + q]     * qscale);
        qf[ks][1] = f2tf(Qs[(rbase + g + 8) * LDS_ + 8 * ks + q]     * qscale);
        qf[ks][2] = f2tf(Qs[(rbase + g)     * LDS_ + 8 * ks + q + 4] * qscale);
        qf[ks][3] = f2tf(Qs[(rbase + g + 8) * LDS_ + 8 * ks + q + 4] * qscale);
    }

    float o[8][4];
#pragma unroll
    for (int i = 0; i < 8; i++)
#pragma unroll
        for (int k = 0; k < 4; k++) o[i][k] = 0.0f;
    float m0 = -INFINITY, m1 = -INFINITY, l0 = 0.0f, l1 = 0.0f;

    const int src1 = (lane & ~3) | (q >> 1);
    const int src2 = src1 + 2;
    const bool odd = q & 1;

    for (int j = 0; j < SS / 64; j++) {
        asm volatile("cp.async.wait_group 1;");
        __syncthreads();
        const float* K = (j & 1) ? Kbuf1 : Kbuf0;
        const float* V = (j & 1) ? Vbuf1 : Vbuf0;

        float s[8][4];
#pragma unroll
        for (int nt = 0; nt < 8; nt++)
            s[nt][0] = s[nt][1] = s[nt][2] = s[nt][3] = 0.0f;
#pragma unroll
        for (int ks = 0; ks < 8; ks++) {
#pragma unroll
            for (int p = 0; p < 4; p++) {
                unsigned kb[4];
                ldsm4(kb, K + (p * 16 + b_row) * LDS_ + 8 * ks + b_col);
                mma8(s[2 * p],     qf[ks], kb[0], kb[1]);
                mma8(s[2 * p + 1], qf[ks], kb[2], kb[3]);
            }
        }

        float mx0 = -INFINITY, mx1 = -INFINITY;
#pragma unroll
        for (int nt = 0; nt < 8; nt++) {
            mx0 = fmaxf(mx0, fmaxf(s[nt][0], s[nt][1]));
            mx1 = fmaxf(mx1, fmaxf(s[nt][2], s[nt][3]));
        }
        mx0 = fmaxf(mx0, __shfl_xor_sync(0xffffffffu, mx0, 1));
        mx0 = fmaxf(mx0, __shfl_xor_sync(0xffffffffu, mx0, 2));
        mx1 = fmaxf(mx1, __shfl_xor_sync(0xffffffffu, mx1, 1));
        mx1 = fmaxf(mx1, __shfl_xor_sync(0xffffffffu, mx1, 2));
        float mn0 = fmaxf(m0, mx0), mn1 = fmaxf(m1, mx1);
        float cr0 = ex2f(m0 - mn0), cr1 = ex2f(m1 - mn1);
        float rs0 = 0.0f, rs1 = 0.0f;
#pragma unroll
        for (int nt = 0; nt < 8; nt++) {
            s[nt][0] = ex2f(s[nt][0] - mn0);
            s[nt][1] = ex2f(s[nt][1] - mn0);
            s[nt][2] = ex2f(s[nt][2] - mn1);
            s[nt][3] = ex2f(s[nt][3] - mn1);
            rs0 += s[nt][0] + s[nt][1];
            rs1 += s[nt][2] + s[nt][3];
        }
        rs0 += __shfl_xor_sync(0xffffffffu, rs0, 1);
        rs0 += __shfl_xor_sync(0xffffffffu, rs0, 2);
        rs1 += __shfl_xor_sync(0xffffffffu, rs1, 1);
        rs1 += __shfl_xor_sync(0xffffffffu, rs1, 2);
        l0 = l0 * cr0 + rs0;
        l1 = l1 * cr1 + rs1;
#pragma unroll
        for (int nt = 0; nt < 8; nt++) {
            o[nt][0] *= cr0; o[nt][1] *= cr0;
            o[nt][2] *= cr1; o[nt][3] *= cr1;
        }
        m0 = mn0; m1 = mn1;

        unsigned pf[8][4];
#pragma unroll
        for (int nt = 0; nt < 8; nt++) {
            float v00 = __shfl_sync(0xffffffffu, s[nt][0], src1);
            float v01 = __shfl_sync(0xffffffffu, s[nt][1], src1);
            float v10 = __shfl_sync(0xffffffffu, s[nt][2], src1);
            float v11 = __shfl_sync(0xffffffffu, s[nt][3], src1);
            float w00 = __shfl_sync(0xffffffffu, s[nt][0], src2);
            float w01 = __shfl_sync(0xffffffffu, s[nt][1], src2);
            float w10 = __shfl_sync(0xffffffffu, s[nt][2], src2);
            float w11 = __shfl_sync(0xffffffffu, s[nt][3], src2);
            pf[nt][0] = f2tf(odd ? v01 : v00);
            pf[nt][1] = f2tf(odd ? v11 : v10);
            pf[nt][2] = f2tf(odd ? w01 : w00);
            pf[nt][3] = f2tf(odd ? w11 : w10);
        }

#pragma unroll
        for (int t = 0; t < 8; t++) {
#pragma unroll
            for (int p = 0; p < 4; p++) {
                unsigned vb[4];
                ldsm4(vb, V + (p * 16 + b_row) * LDS_ + 8 * t + b_col);
                mma8(o[2 * p],     pf[t], vb[0], vb[1]);
                mma8(o[2 * p + 1], pf[t], vb[2], vb[3]);
            }
        }

        __syncthreads();
        if (j + 2 < SS / 64) {
            float* Kd = (j & 1) ? Kbuf1 : Kbuf0;
            float* Vd = (j & 1) ? Vbuf1 : Vbuf0;
#pragma unroll
            for (int i = 0; i < 4; i++) {
                int idx = tid + i * 256;
                int r = idx >> 4, c = (idx & 15) * 4;
                cp16(Kd + r * LDS_ + c, Kg + (size_t)((j + 2) * 64 + r) * 64 + c);
                cp16(Vd + r * LDS_ + c, Vg + (size_t)r * SS + (j + 2) * 64 + c);
            }
        }
        asm volatile("cp.async.commit_group;");
    }

    float inv0 = 1.0f / l0, inv1 = 1.0f / l1;
    int b = bh / HH, h = bh % HH;
    size_t row0 = (size_t)b * SS + q0 + rbase + g;
    float* d0 = g_O + row0 * EE + h * DD;
    float* d1 = d0 + 8 * EE;
#pragma unroll
    for (int nt2 = 0; nt2 < 8; nt2++) {
        float2 u;
        u.x = __uint_as_float(f2tf(o[nt2][0] * inv0));
        u.y = __uint_as_float(f2tf(o[nt2][1] * inv0));
        *(float2*)(d0 + 8 * nt2 + 2 * q) = u;
        float2 w;
        w.x = __uint_as_float(f2tf(o[nt2][2] * inv1));
        w.y = __uint_as_float(f2tf(o[nt2][3] * inv1));
        *(float2*)(d1 + 8 * nt2 + 2 * q) = w;
    }
}

// ---------------------------------------------------------------------------
extern "C" void kernel_launch(void* const* d_in, const int* in_sizes, int n_in,
                              void* d_out, int out_size)
{
    const float* x  = (const float*)d_in[0];
    const float* Wq = (const float*)d_in[1];
    const float* bq = (const float*)d_in[2];
    const float* Wk = (const float*)d_in[3];
    const float* bk = (const float*)d_in[4];
    const float* Wv = (const float*)d_in[5];
    const float* bv = (const float*)d_in[6];
    const float* Wo = (const float*)d_in[7];
    const float* bo = (const float*)d_in[8];
    float* out = (float*)d_out;

    (void)in_sizes; (void)n_in; (void)out_size;

    const int gemm_smem = 2 * 2 * GSTAGE * sizeof(float);   // 73728
    cudaFuncSetAttribute(gemm_tc<0>, cudaFuncAttributeMaxDynamicSharedMemorySize, gemm_smem);
    cudaFuncSetAttribute(gemm_tc<1>, cudaFuncAttributeMaxDynamicSharedMemorySize, gemm_smem);
    const int attn_smem = (QSTAGE_F + 4 * TILE_F) * sizeof(float);
    cudaFuncSetAttribute(attn_kernel, cudaFuncAttributeMaxDynamicSharedMemorySize, attn_smem);

    round_x_kernel<<<MM * EE / 4 / 256, 256>>>((const float4*)x);

    dim3 gq(MM / 128, EE / 128, 3);
    gemm_tc<0><<<gq, 128, gemm_smem>>>(Wq, bq, Wk, bk, Wv, bv, nullptr);

    attn_kernel<<<dim3(SS / 128, BB * HH), 256, attn_smem>>>();

    dim3 go(MM / 128, EE / 128, 1);
    gemm_tc<1><<<go, 128, gemm_smem>>>(Wo, bo, nullptr, nullptr, nullptr, nullptr, out);
}

// round 11
// speedup vs baseline: 1.3153x; 1.0548x over previous
#include <cuda_runtime.h>
#include <math.h>

#define BB 2
#define SS 2048
#define EE 1024
#define HH 16
#define DD 64
#define MM (BB * SS)   // 4096

__device__ float g_Q[MM * EE];   // [B,H,S,D] tf32-rounded
__device__ float g_K[MM * EE];   // [B,H,S,D] tf32-rounded
__device__ float g_V[MM * EE];   // [B,H,D,S] tf32-rounded (transposed)
__device__ float g_O[MM * EE];   // [M,E] tf32-rounded (X, then attn O)

// ---------------------------------------------------------------------------
// helpers
// ---------------------------------------------------------------------------
__device__ __forceinline__ unsigned f2tf(float f) {
    unsigned u; asm("cvt.rna.tf32.f32 %0, %1;" : "=r"(u) : "f"(f)); return u;
}
__device__ __forceinline__ float ex2f(float x) {
    float y; asm("ex2.approx.f32 %0, %1;" : "=f"(y) : "f"(x)); return y;
}
__device__ __forceinline__ void mma8(float* c, const unsigned* a, unsigned b0, unsigned b1) {
    asm volatile(
        "mma.sync.aligned.m16n8k8.row.col.f32.tf32.tf32.f32 "
        "{%0,%1,%2,%3}, {%4,%5,%6,%7}, {%8,%9}, {%0,%1,%2,%3};"
        : "+f"(c[0]), "+f"(c[1]), "+f"(c[2]), "+f"(c[3])
        : "r"(a[0]), "r"(a[1]), "r"(a[2]), "r"(a[3]), "r"(b0), "r"(b1));
}
__device__ __forceinline__ void cp16(float* smem, const float* gmem) {
    unsigned s = (unsigned)__cvta_generic_to_shared(smem);
    asm volatile("cp.async.cg.shared.global [%0], [%1], 16;" :: "r"(s), "l"(gmem));
}
__device__ __forceinline__ void ldsm4(unsigned* r, const float* p) {
    unsigned a = (unsigned)__cvta_generic_to_shared(p);
    asm volatile("ldmatrix.sync.aligned.m8n8.x4.shared.b16 {%0,%1,%2,%3}, [%4];"
                 : "=r"(r[0]), "=r"(r[1]), "=r"(r[2]), "=r"(r[3]) : "r"(a));
}

// ---------------------------------------------------------------------------
// round x -> tf32, written straight into g_O
// ---------------------------------------------------------------------------
__global__ void __launch_bounds__(256) round_x_kernel(const float4* __restrict__ src)
{
    int i = blockIdx.x * 256 + threadIdx.x;
    float4 v = src[i];
    v.x = __uint_as_float(f2tf(v.x)); v.y = __uint_as_float(f2tf(v.y));
    v.z = __uint_as_float(f2tf(v.z)); v.w = __uint_as_float(f2tf(v.w));
    ((float4*)g_O)[i] = v;
}

// ---------------------------------------------------------------------------
// Tensor-core NT GEMM (unchanged from R10): 128x128x32 CTA tile, 128 threads,
// 4 warps of 64x64, 3 CTAs/SM, 2-stage cp.async ring.
// ---------------------------------------------------------------------------
#define GLD 36
#define GSTAGE (128 * GLD)

template <int MODE>
__global__ void __launch_bounds__(128, 3)
gemm_tc(const float* __restrict__ W0, const float* __restrict__ b0v,
        const float* __restrict__ W1, const float* __restrict__ b1v,
        const float* __restrict__ W2, const float* __restrict__ b2v,
        float* __restrict__ Yout)
{
    extern __shared__ float sh[];

    const float* Ag = g_O;
    const float* W; const float* bias; int z = 0;
    if (MODE == 0) {
        z    = blockIdx.z;
        W    = (z == 0) ? W0 : (z == 1) ? W1 : W2;
        bias = (z == 0) ? b0v : (z == 1) ? b1v : b2v;
    } else { W = W0; bias = b0v; }

    const int tid  = threadIdx.x;
    const int warp = tid >> 5;
    const int lane = tid & 31;
    const int g    = lane >> 2;
    const int q    = lane & 3;
    const int m0   = blockIdx.x * 128;
    const int n0   = blockIdx.y * 128;
    const int wm   = (warp >> 1) * 64;
    const int wn   = (warp & 1) * 64;

    const int a_row = (lane & 15);
    const int a_col = (lane & 16) >> 2;
    const int b_row = (lane & 7) + ((lane & 16) >> 1);
    const int b_col = (lane & 8) >> 1;

    float acc[4][8][4];
#pragma unroll
    for (int mt = 0; mt < 4; mt++)
#pragma unroll
        for (int nt = 0; nt < 8; nt++)
#pragma unroll
            for (int t = 0; t < 4; t++) acc[mt][nt][t] = 0.0f;

    auto load_stage = [&](int k0, float* As, float* Bs) {
#pragma unroll
        for (int i = 0; i < 8; i++) {
            int idx = tid + i * 128;
            int row = idx >> 3, c4 = (idx & 7) * 4;
            cp16(As + row * GLD + c4, Ag + (size_t)(m0 + row) * EE + k0 + c4);
        }
#pragma unroll
        for (int i = 0; i < 8; i++) {
            int idx = tid + i * 128;
            int row = idx >> 3, c4 = (idx & 7) * 4;
            cp16(Bs + row * GLD + c4, W + (size_t)(n0 + row) * EE + k0 + c4);
        }
    };

    load_stage(0, sh, sh + GSTAGE);
    asm volatile("cp.async.commit_group;");
    load_stage(32, sh + 2 * GSTAGE, sh + 3 * GSTAGE);
    asm volatile("cp.async.commit_group;");

    const int NITER = EE / 32;
    for (int it = 0; it < NITER; it++) {
        asm volatile("cp.async.wait_group 1;");
        __syncthreads();
        const float* As = sh + (it & 1) * 2 * GSTAGE;
        const float* Bs = As + GSTAGE;

#pragma unroll
        for (int kk = 0; kk < 32; kk += 8) {
            unsigned af[4][4];
#pragma unroll
            for (int mt = 0; mt < 4; mt++)
                ldsm4(af[mt], As + (wm + mt * 16 + a_row) * GLD + kk + a_col);
#pragma unroll
            for (int p = 0; p < 4; p++) {
                unsigned bq[4];
                ldsm4(bq, Bs + (wn + p * 16 + b_row) * GLD + kk + b_col);
                unsigned c0 = f2tf(__uint_as_float(bq[0]));
                unsigned c1 = f2tf(__uint_as_float(bq[1]));
                unsigned c2 = f2tf(__uint_as_float(bq[2]));
                unsigned c3 = f2tf(__uint_as_float(bq[3]));
#pragma unroll
                for (int mt = 0; mt < 4; mt++) {
                    mma8(acc[mt][2 * p],     af[mt], c0, c1);
                    mma8(acc[mt][2 * p + 1], af[mt], c2, c3);
                }
            }
        }

        __syncthreads();
        if (it + 2 < NITER) {
            float* As2 = sh + (it & 1) * 2 * GSTAGE;
            load_stage((it + 2) * 32, As2, As2 + GSTAGE);
        }
        asm volatile("cp.async.commit_group;");
    }

#pragma unroll
    for (int mt = 0; mt < 4; mt++) {
#pragma unroll
        for (int nt = 0; nt < 8; nt++) {
            int r = m0 + wm + mt * 16 + g;
            int c = n0 + wn + nt * 8 + 2 * q;
            float bx = bias[c], by = bias[c + 1];
            float v0 = acc[mt][nt][0] + bx, v1 = acc[mt][nt][1] + by;
            float v2 = acc[mt][nt][2] + bx, v3 = acc[mt][nt][3] + by;
            if (MODE == 0) {
                int b = r >> 11, s = r & (SS - 1);
                int h = c >> 6, d = c & 63;
                if (z == 2) {
                    float* dst = g_V + (((size_t)(b * HH + h)) * DD + d) * SS + s;
                    dst[0]      = __uint_as_float(f2tf(v0));
                    dst[SS]     = __uint_as_float(f2tf(v1));
                    dst[8]      = __uint_as_float(f2tf(v2));
                    dst[SS + 8] = __uint_as_float(f2tf(v3));
                } else {
                    float* dst = (z == 0) ? g_Q : g_K;
                    dst += (((size_t)(b * HH + h)) * SS + s) * DD + d;
                    float2 u0; u0.x = __uint_as_float(f2tf(v0)); u0.y = __uint_as_float(f2tf(v1));
                    float2 u1; u1.x = __uint_as_float(f2tf(v2)); u1.y = __uint_as_float(f2tf(v3));
                    *(float2*)dst = u0;
                    *(float2*)(dst + 8 * DD) = u1;
                }
            } else {
                float* dst = Yout + (size_t)r * EE + c;
                float2 u0; u0.x = v0; u0.y = v1;
                float2 u1; u1.x = v2; u1.y = v3;
                *(float2*)dst = u0;
                *(float2*)(dst + 8 * EE) = u1;
            }
        }
    }
}

// ---------------------------------------------------------------------------
// Flash attention: 256 q-rows per CTA, 8 warps x 32 rows (2 subtiles of 16).
// K/V fragment loads per warp unchanged vs 16-row version -> bytes/MAC halved.
// P fragments overwrite score regs in place to cap register pressure.
// ---------------------------------------------------------------------------
#define LDS_ 68
#define TILE_F (64 * LDS_)
#define QROWS 256
#define QSTAGE_F (QROWS * LDS_)

__global__ void __launch_bounds__(256, 1) attn_kernel()
{
    extern __shared__ float sh[];
    float* Qs = sh;
    float* Kbuf0 = sh + QSTAGE_F;
    float* Vbuf0 = Kbuf0 + TILE_F;
    float* Kbuf1 = Vbuf0 + TILE_F;
    float* Vbuf1 = Kbuf1 + TILE_F;

    const int tid  = threadIdx.x;
    const int warp = tid >> 5;
    const int lane = tid & 31;
    const int g    = lane >> 2;
    const int q    = lane & 3;
    const int bh   = blockIdx.y;
    const int q0   = blockIdx.x * QROWS;

    const float* Qg = g_Q + (size_t)bh * SS * DD;
    const float* Kg = g_K + (size_t)bh * SS * DD;
    const float* Vg = g_V + (size_t)bh * SS * DD;   // transposed [D][S]

    const int b_row = (lane & 7) + ((lane & 16) >> 1);
    const int b_col = (lane & 8) >> 1;

#pragma unroll
    for (int t = 0; t < 2; t++) {
        float* Kd = t ? Kbuf1 : Kbuf0;
        float* Vd = t ? Vbuf1 : Vbuf0;
#pragma unroll
        for (int i = 0; i < 4; i++) {
            int idx = tid + i * 256;
            int r = idx >> 4, c = (idx & 15) * 4;
            cp16(Kd + r * LDS_ + c, Kg + (size_t)(t * 64 + r) * 64 + c);
            cp16(Vd + r * LDS_ + c, Vg + (size_t)r * SS + t * 64 + c);
        }
        asm volatile("cp.async.commit_group;");
    }

    // stage Q (256 rows x 64 cols)
#pragma unroll
    for (int i = 0; i < 16; i++) {
        int idx = tid + i * 256;
        int r = idx >> 4, c = (idx & 15) * 4;
        *(float4*)(Qs + r * LDS_ + c) = *(const float4*)(Qg + (size_t)(q0 + r) * 64 + c);
    }
    __syncthreads();

    const float qscale = 0.125f * 1.44269504088896340736f;  // D^-0.5 * log2(e)
    const int rbase = warp * 32;
    unsigned qf[2][8][4];
#pragma unroll
    for (int mt = 0; mt < 2; mt++) {
        int rb = rbase + mt * 16;
#pragma unroll
        for (int ks = 0; ks < 8; ks++) {
            qf[mt][ks][0] = f2tf(Qs[(rb + g)     * LDS_ + 8 * ks + q]     * qscale);
            qf[mt][ks][1] = f2tf(Qs[(rb + g + 8) * LDS_ + 8 * ks + q]     * qscale);
            qf[mt][ks][2] = f2tf(Qs[(rb + g)     * LDS_ + 8 * ks + q + 4] * qscale);
            qf[mt][ks][3] = f2tf(Qs[(rb + g + 8) * LDS_ + 8 * ks + q + 4] * qscale);
        }
    }

    float o[2][8][4];
#pragma unroll
    for (int mt = 0; mt < 2; mt++)
#pragma unroll
        for (int i = 0; i < 8; i++)
#pragma unroll
            for (int k = 0; k < 4; k++) o[mt][i][k] = 0.0f;
    float mrow[2][2], lrow[2][2];
#pragma unroll
    for (int mt = 0; mt < 2; mt++) {
        mrow[mt][0] = mrow[mt][1] = -INFINITY;
        lrow[mt][0] = lrow[mt][1] = 0.0f;
    }

    const int src1 = (lane & ~3) | (q >> 1);
    const int src2 = src1 + 2;
    const bool odd = q & 1;

    for (int j = 0; j < SS / 64; j++) {
        asm volatile("cp.async.wait_group 1;");
        __syncthreads();
        const float* K = (j & 1) ? Kbuf1 : Kbuf0;
        const float* V = (j & 1) ? Vbuf1 : Vbuf0;

        // ---- S = (Q*scale) K^T : K fragments shared across both subtiles ----
        float s[2][8][4];
#pragma unroll
        for (int mt = 0; mt < 2; mt++)
#pragma unroll
            for (int nt = 0; nt < 8; nt++)
                s[mt][nt][0] = s[mt][nt][1] = s[mt][nt][2] = s[mt][nt][3] = 0.0f;
#pragma unroll
        for (int ks = 0; ks < 8; ks++) {
#pragma unroll
            for (int p = 0; p < 4; p++) {
                unsigned kb[4];
                ldsm4(kb, K + (p * 16 + b_row) * LDS_ + 8 * ks + b_col);
#pragma unroll
                for (int mt = 0; mt < 2; mt++) {
                    mma8(s[mt][2 * p],     qf[mt][ks], kb[0], kb[1]);
                    mma8(s[mt][2 * p + 1], qf[mt][ks], kb[2], kb[3]);
                }
            }
        }

        // ---- online softmax per subtile ----
#pragma unroll
        for (int mt = 0; mt < 2; mt++) {
            float mx0 = -INFINITY, mx1 = -INFINITY;
#pragma unroll
            for (int nt = 0; nt < 8; nt++) {
                mx0 = fmaxf(mx0, fmaxf(s[mt][nt][0], s[mt][nt][1]));
                mx1 = fmaxf(mx1, fmaxf(s[mt][nt][2], s[mt][nt][3]));
            }
            mx0 = fmaxf(mx0, __shfl_xor_sync(0xffffffffu, mx0, 1));
            mx0 = fmaxf(mx0, __shfl_xor_sync(0xffffffffu, mx0, 2));
            mx1 = fmaxf(mx1, __shfl_xor_sync(0xffffffffu, mx1, 1));
            mx1 = fmaxf(mx1, __shfl_xor_sync(0xffffffffu, mx1, 2));
            float mn0 = fmaxf(mrow[mt][0], mx0), mn1 = fmaxf(mrow[mt][1], mx1);
            float cr0 = ex2f(mrow[mt][0] - mn0), cr1 = ex2f(mrow[mt][1] - mn1);
            float rs0 = 0.0f, rs1 = 0.0f;
#pragma unroll
            for (int nt = 0; nt < 8; nt++) {
                s[mt][nt][0] = ex2f(s[mt][nt][0] - mn0);
                s[mt][nt][1] = ex2f(s[mt][nt][1] - mn0);
                s[mt][nt][2] = ex2f(s[mt][nt][2] - mn1);
                s[mt][nt][3] = ex2f(s[mt][nt][3] - mn1);
                rs0 += s[mt][nt][0] + s[mt][nt][1];
                rs1 += s[mt][nt][2] + s[mt][nt][3];
            }
            rs0 += __shfl_xor_sync(0xffffffffu, rs0, 1);
            rs0 += __shfl_xor_sync(0xffffffffu, rs0, 2);
            rs1 += __shfl_xor_sync(0xffffffffu, rs1, 1);
            rs1 += __shfl_xor_sync(0xffffffffu, rs1, 2);
            lrow[mt][0] = lrow[mt][0] * cr0 + rs0;
            lrow[mt][1] = lrow[mt][1] * cr1 + rs1;
#pragma unroll
            for (int nt = 0; nt < 8; nt++) {
                o[mt][nt][0] *= cr0; o[mt][nt][1] *= cr0;
                o[mt][nt][2] *= cr1; o[mt][nt][3] *= cr1;
            }
            mrow[mt][0] = mn0; mrow[mt][1] = mn1;

            // permute P (C layout) -> A fragments IN PLACE over s (tf32 bits)
#pragma unroll
            for (int nt = 0; nt < 8; nt++) {
                float v00 = __shfl_sync(0xffffffffu, s[mt][nt][0], src1);
                float v01 = __shfl_sync(0xffffffffu, s[mt][nt][1], src1);
                float v10 = __shfl_sync(0xffffffffu, s[mt][nt][2], src1);
                float v11 = __shfl_sync(0xffffffffu, s[mt][nt][3], src1);
                float w00 = __shfl_sync(0xffffffffu, s[mt][nt][0], src2);
                float w01 = __shfl_sync(0xffffffffu, s[mt][nt][1], src2);
                float w10 = __shfl_sync(0xffffffffu, s[mt][nt][2], src2);
                float w11 = __shfl_sync(0xffffffffu, s[mt][nt][3], src2);
                s[mt][nt][0] = __uint_as_float(f2tf(odd ? v01 : v00));
                s[mt][nt][1] = __uint_as_float(f2tf(odd ? v11 : v10));
                s[mt][nt][2] = __uint_as_float(f2tf(odd ? w01 : w00));
                s[mt][nt][3] = __uint_as_float(f2tf(odd ? w11 : w10));
            }
        }

        // ---- O += P V : V fragments shared across both subtiles ----
#pragma unroll
        for (int t = 0; t < 8; t++) {
#pragma unroll
            for (int p = 0; p < 4; p++) {
                unsigned vb[4];
                ldsm4(vb, V + (p * 16 + b_row) * LDS_ + 8 * t + b_col);
#pragma unroll
                for (int mt = 0; mt < 2; mt++) {
                    unsigned pa[4] = {
                        __float_as_uint(s[mt][t][0]), __float_as_uint(s[mt][t][1]),
                        __float_as_uint(s[mt][t][2]), __float_as_uint(s[mt][t][3]) };
                    mma8(o[mt][2 * p],     pa, vb[0], vb[1]);
                    mma8(o[mt][2 * p + 1], pa, vb[2], vb[3]);
                }
            }
        }

        __syncthreads();
        if (j + 2 < SS / 64) {
            float* Kd = (j & 1) ? Kbuf1 : Kbuf0;
            float* Vd = (j & 1) ? Vbuf1 : Vbuf0;
#pragma unroll
            for (int i = 0; i < 4; i++) {
                int idx = tid + i * 256;
                int r = idx >> 4, c = (idx & 15) * 4;
                cp16(Kd + r * LDS_ + c, Kg + (size_t)((j + 2) * 64 + r) * 64 + c);
                cp16(Vd + r * LDS_ + c, Vg + (size_t)r * SS + (j + 2) * 64 + c);
            }
        }
        asm volatile("cp.async.commit_group;");
    }

    // ---- epilogue ----
    int b = bh / HH, h = bh % HH;
#pragma unroll
    for (int mt = 0; mt < 2; mt++) {
        float inv0 = 1.0f / lrow[mt][0], inv1 = 1.0f / lrow[mt][1];
        size_t row0 = (size_t)b * SS + q0 + rbase + mt * 16 + g;
        float* d0 = g_O + row0 * EE + h * DD;
        float* d1 = d0 + 8 * EE;
#pragma unroll
        for (int nt2 = 0; nt2 < 8; nt2++) {
            float2 u;
            u.x = __uint_as_float(f2tf(o[mt][nt2][0] * inv0));
            u.y = __uint_as_float(f2tf(o[mt][nt2][1] * inv0));
            *(float2*)(d0 + 8 * nt2 + 2 * q) = u;
            float2 w;
            w.x = __uint_as_float(f2tf(o[mt][nt2][2] * inv1));
            w.y = __uint_as_float(f2tf(o[mt][nt2][3] * inv1));
            *(float2*)(d1 + 8 * nt2 + 2 * q) = w;
        }
    }
}

// ---------------------------------------------------------------------------
extern "C" void kernel_launch(void* const* d_in, const int* in_sizes, int n_in,
                              void* d_out, int out_size)
{
    const float* x  = (const float*)d_in[0];
    const float* Wq = (const float*)d_in[1];
    const float* bq = (const float*)d_in[2];
    const float* Wk = (const float*)d_in[3];
    const float* bk = (const float*)d_in[4];
    const float* Wv = (const float*)d_in[5];
    const float* bv = (const float*)d_in[6];
    const float* Wo = (const float*)d_in[7];
    const float* bo = (const float*)d_in[8];
    float* out = (float*)d_out;

    (void)in_sizes; (void)n_in; (void)out_size;

    const int gemm_smem = 2 * 2 * GSTAGE * sizeof(float);   // 73728
    cudaFuncSetAttribute(gemm_tc<0>, cudaFuncAttributeMaxDynamicSharedMemorySize, gemm_smem);
    cudaFuncSetAttribute(gemm_tc<1>, cudaFuncAttributeMaxDynamicSharedMemorySize, gemm_smem);
    const int attn_smem = (QSTAGE_F + 4 * TILE_F) * sizeof(float);  // 139264
    cudaFuncSetAttribute(attn_kernel, cudaFuncAttributeMaxDynamicSharedMemorySize, attn_smem);

    round_x_kernel<<<MM * EE / 4 / 256, 256>>>((const float4*)x);

    dim3 gq(MM / 128, EE / 128, 3);
    gemm_tc<0><<<gq, 128, gemm_smem>>>(Wq, bq, Wk, bk, Wv, bv, nullptr);

    attn_kernel<<<dim3(SS / QROWS, BB * HH), 256, attn_smem>>>();

    dim3 go(MM / 128, EE / 128, 1);
    gemm_tc<1><<<go, 128, gemm_smem>>>(Wo, bo, nullptr, nullptr, nullptr, nullptr, out);
}